// round 14
// baseline (speedup 1.0000x reference)
#include <cuda_runtime.h>
#include <cuda_fp16.h>
#include <cstdint>

#define Nn 100000
#define Ee 1600000
#define NBLK 98            // ceil(Nn/1024)
#define FULL 0xffffffffu
#define KB 782             // conv blocks per graph
#define NT 6250            // 16-row tiles per graph
#define GB 1184

// ---------------- scratch (static __device__, zero-initialized) ----------------
__device__ int    g_deg[4*Nn];         // out1, in1, out2, in2 (re-zeroed by k_final tail)
__device__ float  g_norm[4*Nn];        // ns1, nd1, ns2, nd2
__device__ int    g_rp[2*(Nn+1)];      // partial CSR row ptrs (scan1 block-local)
__device__ int    g_rpf[2*(Nn+1)];     // final CSR row ptrs
__device__ int    g_col[2*Ee];         // (src*32) per dst-sorted edge
__device__ int    g_rank[2*Ee];        // per-edge rank within dst bucket
__device__ int    g_bsum[2*NBLK];      // scan block sums
__device__ __half g_sxA[2*Nn*64];
__device__ __half g_sxB[2*Nn*64];
__device__ float  g_h[2*Nn*64];
__device__ float  g_y[Nn*64];
__device__ float  g_stats[384];

// degree count + in-bucket rank recording (4 edges/thread, int4)
__global__ void k_degrank(const int4* __restrict__ s1, const int4* __restrict__ d1,
                          const int4* __restrict__ s2, const int4* __restrict__ d2){
  int t = blockIdx.x*blockDim.x + threadIdx.x;
  if (t >= Ee/4) return;
  int4 a=s1[t], b=d1[t], c=s2[t], d=d2[t];
  atomicAdd(&g_deg[a.x],1); atomicAdd(&g_deg[a.y],1);
  atomicAdd(&g_deg[a.z],1); atomicAdd(&g_deg[a.w],1);
  int4 r1;
  r1.x=atomicAdd(&g_deg[Nn+b.x],1); r1.y=atomicAdd(&g_deg[Nn+b.y],1);
  r1.z=atomicAdd(&g_deg[Nn+b.z],1); r1.w=atomicAdd(&g_deg[Nn+b.w],1);
  ((int4*)g_rank)[t]=r1;
  atomicAdd(&g_deg[2*Nn+c.x],1); atomicAdd(&g_deg[2*Nn+c.y],1);
  atomicAdd(&g_deg[2*Nn+c.z],1); atomicAdd(&g_deg[2*Nn+c.w],1);
  int4 r2;
  r2.x=atomicAdd(&g_deg[3*Nn+d.x],1); r2.y=atomicAdd(&g_deg[3*Nn+d.y],1);
  r2.z=atomicAdd(&g_deg[3*Nn+d.z],1); r2.w=atomicAdd(&g_deg[3*Nn+d.w],1);
  ((int4*)(g_rank+Ee))[t]=r2;
}

// block-local inclusive scan of in-degree + norms
__global__ void k_scan1(){
  __shared__ int sh[1024];
  int g = blockIdx.x / NBLK;
  int b = blockIdx.x - g*NBLK;
  const int* degin  = g_deg + 2*Nn*g + Nn;
  const int* degout = g_deg + 2*Nn*g;
  int* rp = g_rp + g*(Nn+1);
  int t = threadIdx.x;
  int i = b*1024 + t;
  int v = (i<Nn)? degin[i] : 0;
  if (i<Nn){
    int dou = degout[i]; if (dou<1) dou=1;
    int din = v;         if (din<1) din=1;
    g_norm[2*Nn*g + i]      = rsqrtf((float)dou);   // ns
    g_norm[2*Nn*g + Nn + i] = rsqrtf((float)din);   // nd
  }
  sh[t]=v; __syncthreads();
  #pragma unroll
  for (int off=1; off<1024; off<<=1){
    int x = (t>=off)? sh[t-off] : 0;
    __syncthreads();
    sh[t]+=x;
    __syncthreads();
  }
  if (i<Nn) rp[i] = sh[t]-v;                  // block-local exclusive
  if (t==1023) g_bsum[g*NBLK + b] = sh[t];
}

// fused: per-block redundant bsum scan + CSR fill (atomic-free) + final rp + prescale + stats zero
__global__ void __launch_bounds__(256) k_fillpre(
    const int* __restrict__ s1, const int* __restrict__ d1,
    const int* __restrict__ s2, const int* __restrict__ d2,
    const float4* __restrict__ x1, const float4* __restrict__ x2){
  __shared__ int sh[256];
  __shared__ int pref[256];    // pref[g*128 + blk] = exclusive prefix of bsum
  int tid = threadIdx.x;
  int h = tid>>7, li = tid&127;
  int v = (li<NBLK)? g_bsum[h*NBLK+li] : 0;
  sh[tid]=v; __syncthreads();
  #pragma unroll
  for (int off=1; off<128; off<<=1){
    int x = (li>=off)? sh[tid-off] : 0;
    __syncthreads();
    sh[tid]+=x;
    __syncthreads();
  }
  pref[tid] = sh[tid]-v;
  __syncthreads();
  int t = blockIdx.x*256 + tid;
  if (t < 384) g_stats[t]=0.f;
  if (t < 2*Ee){
    int g = t >= Ee;
    int e = t - g*Ee;
    int d = g ? d2[e] : d1[e];
    int s = g ? s2[e] : s1[e];
    int pos = g_rp[g*(Nn+1)+d] + pref[g*128 + (d>>10)] + g_rank[g*Ee+e];
    g_col[g*Ee+pos] = s*32;
  } else if (t < 2*Ee + 2*Nn*16){
    int i = t - 2*Ee;
    int g = i >= Nn*16;
    int local = i - g*Nn*16;
    float s = g_norm[2*Nn*g + (local>>4)];
    float4 vv = g ? x2[local] : x1[local];
    __half2 h0 = __floats2half2_rn(vv.x*s, vv.y*s);
    __half2 h1 = __floats2half2_rn(vv.z*s, vv.w*s);
    union { __half2 hh[2]; uint2 u; } pk;
    pk.hh[0]=h0; pk.hh[1]=h1;
    ((uint2*)g_sxA)[i] = pk.u;
  } else {
    int i2 = t - (2*Ee + 2*Nn*16);
    if (i2 < 2*(Nn+1)){
      int g = i2 >= (Nn+1);
      int i = i2 - g*(Nn+1);
      g_rpf[g*(Nn+1)+i] = (i==Nn)? Ee : (g_rp[g*(Nn+1)+i] + pref[g*128 + (i>>10)]);
    }
  }
}

// gather: coalesced col fetch (1 LDG per 32 edges) + shfl broadcast, 8-deep sx unroll.
// col entries pre-scaled (*32). Serial chain per 32 edges: LDG(col)->SHFL->LDG(sx).
#define GATHERC(sx, rp, col, row, ax, ay)                                   \
  { int e0=rp[row], e1=rp[row+1];                                           \
    for (int base=e0; base<e1; base+=32){                                   \
      int n = e1-base; if (n>32) n=32;                                      \
      int cb = (lane<n)? col[base+lane] : 0;                                \
      int k=0;                                                              \
      for (; k+8<=n; k+=8){                                                 \
        int c0=__shfl_sync(FULL,cb,k),   c1=__shfl_sync(FULL,cb,k+1);       \
        int c2=__shfl_sync(FULL,cb,k+2), c3=__shfl_sync(FULL,cb,k+3);       \
        int c4=__shfl_sync(FULL,cb,k+4), c5=__shfl_sync(FULL,cb,k+5);       \
        int c6=__shfl_sync(FULL,cb,k+6), c7=__shfl_sync(FULL,cb,k+7);       \
        __half2 p0=sx[c0+lane], p1=sx[c1+lane];                             \
        __half2 p2=sx[c2+lane], p3=sx[c3+lane];                             \
        __half2 p4=sx[c4+lane], p5=sx[c5+lane];                             \
        __half2 p6=sx[c6+lane], p7=sx[c7+lane];                             \
        float2 v0=__half22float2(p0), v1=__half22float2(p1);                \
        float2 v2=__half22float2(p2), v3=__half22float2(p3);                \
        float2 v4=__half22float2(p4), v5=__half22float2(p5);                \
        float2 v6=__half22float2(p6), v7=__half22float2(p7);                \
        ax += ((v0.x+v1.x)+(v2.x+v3.x))+((v4.x+v5.x)+(v6.x+v7.x));          \
        ay += ((v0.y+v1.y)+(v2.y+v3.y))+((v4.y+v5.y)+(v6.y+v7.y));          \
      }                                                                     \
      for (; k<n; k++){                                                     \
        int c=__shfl_sync(FULL,cb,k);                                       \
        float2 v=__half22float2(sx[c+lane]);                                \
        ax+=v.x; ay+=v.y;                                                   \
      }                                                                     \
    } }

#define LDMX4(a0,a1,a2,a3,addr)                                         \
  asm volatile("ldmatrix.sync.aligned.m8n8.x4.shared.b16 {%0,%1,%2,%3}, [%4];" \
    : "=r"(a0),"=r"(a1),"=r"(a2),"=r"(a3) : "r"(addr))

#define LDMX4T(b0,b1,b2,b3,addr)                                        \
  asm volatile("ldmatrix.sync.aligned.m8n8.x4.trans.shared.b16 {%0,%1,%2,%3}, [%4];" \
    : "=r"(b0),"=r"(b1),"=r"(b2),"=r"(b3) : "r"(addr))

#define MMA16816(d, a0,a1,a2,a3, b0,b1)                                 \
  asm volatile("mma.sync.aligned.m16n8k16.row.col.f32.f16.f16.f32 "     \
    "{%0,%1,%2,%3}, {%4,%5,%6,%7}, {%8,%9}, {%0,%1,%2,%3};"             \
    : "+f"(d[0]),"+f"(d[1]),"+f"(d[2]),"+f"(d[3])                       \
    : "r"(a0),"r"(a1),"r"(a2),"r"(a3), "r"(b0),"r"(b1))

// W-split df16 GEMM core: acc = A*Wh + A*Wl
#define MMA_TILE_WSPLIT(acc, aAddr, wH, wL)                             \
  { _Pragma("unroll")                                                   \
    for (int s=0;s<4;s++){                                              \
      unsigned int a0,a1,a2,a3;                                         \
      LDMX4(a0,a1,a2,a3, (aAddr) + s*32);                               \
      _Pragma("unroll")                                                 \
      for (int jj=0;jj<4;jj++){                                         \
        unsigned int bh0,bh1,bh2,bh3, bl0,bl1,bl2,bl3;                  \
        LDMX4T(bh0,bh1,bh2,bh3, (wH) + s*2048 + jj*32);                 \
        LDMX4T(bl0,bl1,bl2,bl3, (wL) + s*2048 + jj*32);                 \
        MMA16816(acc[2*jj],   a0,a1,a2,a3, bh0,bh1);                    \
        MMA16816(acc[2*jj],   a0,a1,a2,a3, bl0,bl1);                    \
        MMA16816(acc[2*jj+1], a0,a1,a2,a3, bh2,bh3);                    \
        MMA16816(acc[2*jj+1], a0,a1,a2,a3, bl2,bl3);                    \
      }                                                                 \
    } }

// fused conv layer 1 (HMMA, W-split)
__global__ void __launch_bounds__(256,4) k_convA(
    const float* __restrict__ W1,const float* __restrict__ B1,
    const float* __restrict__ W2,const float* __restrict__ B2){
  __shared__ __half  WshH[4096], WshL[4096];
  __shared__ float   bsh[64];
  __shared__ __half2 As[8*512];
  int g = blockIdx.x >= KB;
  const float* W = g? W2:W1;
  const float* B = g? B2:B1;
  int tid=threadIdx.x;
  for (int j=tid;j<4096;j+=256){
    float w=W[j];
    __half hi=__float2half_rn(w);
    WshH[j]=hi;
    WshL[j]=__float2half_rn(w-__half2float(hi));
  }
  if (tid<64) bsh[tid]=B[tid];
  __syncthreads();
  int lane=tid&31, wid=tid>>5;
  const int* rp  = g_rpf + g*(Nn+1);
  const int* col = g_col + g*Ee;
  const __half2* sx = (const __half2*)g_sxA + g*Nn*32;
  __half2* outp = (__half2*)g_sxB + g*Nn*32;
  const float* nd = g_norm + Nn + 2*Nn*g;
  const float* ns = g_norm + 2*Nn*g;
  __half2* myA = As + wid*512;
  unsigned int aBase = (unsigned int)__cvta_generic_to_shared(myA);
  unsigned int wBaseH = (unsigned int)__cvta_generic_to_shared(WshH);
  unsigned int wBaseL = (unsigned int)__cvta_generic_to_shared(WshL);
  int warp = (blockIdx.x - g*KB)*8 + wid;
  for (int t=warp; t<NT; t+=KB*8){
    int R0 = t*16;
    __syncwarp();
    for (int r=0;r<16;r++){
      int row=R0+r;
      float ax=0.f, ay=0.f;
      GATHERC(sx, rp, col, row, ax, ay);
      myA[r*32+lane]=__floats2half2_rn(ax,ay);
    }
    __syncwarp();
    float acc[8][4];
    #pragma unroll
    for (int j=0;j<8;j++){ acc[j][0]=0.f;acc[j][1]=0.f;acc[j][2]=0.f;acc[j][3]=0.f; }
    unsigned int aA = aBase  + (lane&15)*128 + (lane>>4)*16;
    unsigned int wH = wBaseH + (lane&15)*128 + (lane>>4)*16;
    unsigned int wL = wBaseL + (lane&15)*128 + (lane>>4)*16;
    MMA_TILE_WSPLIT(acc, aA, wH, wL);
    int r0 = lane>>2;
    int row0 = R0 + r0, row1 = row0 + 8;
    float nd0=nd[row0], nd1=nd[row1], ns0=ns[row0], ns1=ns[row1];
    #pragma unroll
    for (int j=0;j<8;j++){
      int c0 = j*8 + (lane&3)*2;
      float bb0=bsh[c0], bb1=bsh[c0+1];
      float o00=fmaxf(acc[j][0]*nd0+bb0,0.f)*ns0;
      float o01=fmaxf(acc[j][1]*nd0+bb1,0.f)*ns0;
      float o10=fmaxf(acc[j][2]*nd1+bb0,0.f)*ns1;
      float o11=fmaxf(acc[j][3]*nd1+bb1,0.f)*ns1;
      outp[row0*32 + (c0>>1)] = __floats2half2_rn(o00,o01);
      outp[row1*32 + (c0>>1)] = __floats2half2_rn(o10,o11);
    }
  }
}

// fused conv layer 2 (HMMA, W-split) + stats
__global__ void __launch_bounds__(256,4) k_convB(
    const float* __restrict__ W1,const float* __restrict__ B1,
    const float* __restrict__ W2,const float* __restrict__ B2){
  __shared__ __half  WshH[4096], WshL[4096];
  __shared__ float   bsh[64];
  __shared__ __half2 As[8*512];
  __shared__ float   shs[64], shq[64];
  int g = blockIdx.x >= KB;
  const float* W = g? W2:W1;
  const float* B = g? B2:B1;
  int tid=threadIdx.x;
  for (int j=tid;j<4096;j+=256){
    float w=W[j];
    __half hi=__float2half_rn(w);
    WshH[j]=hi;
    WshL[j]=__float2half_rn(w-__half2float(hi));
  }
  if (tid<64){ bsh[tid]=B[tid]; shs[tid]=0.f; shq[tid]=0.f; }
  __syncthreads();
  int lane=tid&31, wid=tid>>5;
  const int* rp  = g_rpf + g*(Nn+1);
  const int* col = g_col + g*Ee;
  const __half2* sx = (const __half2*)g_sxB + g*Nn*32;
  float2* outp = (float2*)(g_h + g*Nn*64);
  const float* nd = g_norm + Nn + 2*Nn*g;
  __half2* myA = As + wid*512;
  unsigned int aBase = (unsigned int)__cvta_generic_to_shared(myA);
  unsigned int wBaseH = (unsigned int)__cvta_generic_to_shared(WshH);
  unsigned int wBaseL = (unsigned int)__cvta_generic_to_shared(WshL);
  int warp = (blockIdx.x - g*KB)*8 + wid;
  float st[8][4];
  #pragma unroll
  for (int j=0;j<8;j++){ st[j][0]=0.f;st[j][1]=0.f;st[j][2]=0.f;st[j][3]=0.f; }
  for (int t=warp; t<NT; t+=KB*8){
    int R0 = t*16;
    __syncwarp();
    for (int r=0;r<16;r++){
      int row=R0+r;
      float ax=0.f, ay=0.f;
      GATHERC(sx, rp, col, row, ax, ay);
      myA[r*32+lane]=__floats2half2_rn(ax,ay);
    }
    __syncwarp();
    float acc[8][4];
    #pragma unroll
    for (int j=0;j<8;j++){ acc[j][0]=0.f;acc[j][1]=0.f;acc[j][2]=0.f;acc[j][3]=0.f; }
    unsigned int aA = aBase  + (lane&15)*128 + (lane>>4)*16;
    unsigned int wH = wBaseH + (lane&15)*128 + (lane>>4)*16;
    unsigned int wL = wBaseL + (lane&15)*128 + (lane>>4)*16;
    MMA_TILE_WSPLIT(acc, aA, wH, wL);
    int r0 = lane>>2;
    int row0 = R0 + r0, row1 = row0 + 8;
    float nd0=nd[row0], nd1=nd[row1];
    #pragma unroll
    for (int j=0;j<8;j++){
      int c0 = j*8 + (lane&3)*2;
      float bb0=bsh[c0], bb1=bsh[c0+1];
      float o00=acc[j][0]*nd0+bb0;
      float o01=acc[j][1]*nd0+bb1;
      float o10=acc[j][2]*nd1+bb0;
      float o11=acc[j][3]*nd1+bb1;
      outp[row0*32 + (c0>>1)] = make_float2(o00,o01);
      outp[row1*32 + (c0>>1)] = make_float2(o10,o11);
      st[j][0]+=o00+o10;         st[j][1]+=o01+o11;
      st[j][2]+=o00*o00+o10*o10; st[j][3]+=o01*o01+o11*o11;
    }
  }
  #pragma unroll
  for (int j=0;j<8;j++){
    #pragma unroll
    for (int v=0;v<4;v++){
      float x = st[j][v];
      x += __shfl_xor_sync(FULL, x, 4);
      x += __shfl_xor_sync(FULL, x, 8);
      x += __shfl_xor_sync(FULL, x, 16);
      st[j][v]=x;
    }
    if (lane<4){
      int c = j*8 + lane*2;
      atomicAdd(&shs[c],   st[j][0]);
      atomicAdd(&shs[c+1], st[j][1]);
      atomicAdd(&shq[c],   st[j][2]);
      atomicAdd(&shq[c+1], st[j][3]);
    }
  }
  __syncthreads();
  if (tid<64){
    atomicAdd(&g_stats[g*128+tid],    shs[tid]);
    atomicAdd(&g_stats[g*128+64+tid], shq[tid]);
  }
}

// z1,z2 out; z=(z1+z2)/2; y=z@Wm1+bm1; BN stats of y.
__global__ void __launch_bounds__(256) k_zy(
    const float* __restrict__ Wm1, const float* __restrict__ bm1,
    float* __restrict__ out){
  __shared__ float4 Wq[1024];
  __shared__ float cf[256];
  __shared__ float bsh[64];
  __shared__ float sy[64], sq[64];
  int tid=threadIdx.x;
  for (int idx=tid; idx<1024; idx+=256){
    int kk=idx>>5, j=idx&31;
    Wq[idx]=make_float4(Wm1[(2*kk)*64+j],   Wm1[(2*kk)*64+j+32],
                        Wm1[(2*kk+1)*64+j], Wm1[(2*kk+1)*64+j+32]);
  }
  if (tid<64){
    bsh[tid]=bm1[tid]; sy[tid]=0.f; sq[tid]=0.f;
    #pragma unroll
    for (int gg=0; gg<2; gg++){
      double s = (double)g_stats[gg*128+tid];
      double q = (double)g_stats[gg*128+64+tid];
      double mean = s/(double)Nn;
      double var  = (q - s*s/(double)Nn)/(double)(Nn-1);   // ddof=1
      float is = (float)(1.0/sqrt(var));
      cf[gg*128+tid]    = is;
      cf[gg*128+64+tid] = (float)(-mean)*is;
    }
  }
  __syncthreads();
  int lane=tid&31;
  int warp=(blockIdx.x*blockDim.x+tid)>>5;
  int nw  =(gridDim.x*blockDim.x)>>5;
  const float2* h1 = (const float2*)g_h;
  const float2* h2 = (const float2*)(g_h + Nn*64);
  float2* oz1 = (float2*)out;
  float2* oz2 = (float2*)(out + Nn*64);
  float ls0=0.f,lq0=0.f,ls1=0.f,lq1=0.f;
  int k0=2*lane, k1=2*lane+1;
  float a1x=cf[k0],     a1y=cf[k1],     b1x=cf[64+k0],  b1y=cf[64+k1];
  float a2x=cf[128+k0], a2y=cf[128+k1], b2x=cf[192+k0], b2y=cf[192+k1];
  for (int row=warp; row<Nn; row+=nw){
    float2 v1=h1[row*32+lane], v2=h2[row*32+lane];
    float z1x=v1.x*a1x+b1x, z1y=v1.y*a1y+b1y;
    float z2x=v2.x*a2x+b2x, z2y=v2.y*a2y+b2y;
    oz1[row*32+lane]=make_float2(z1x,z1y);
    oz2[row*32+lane]=make_float2(z2x,z2y);
    float zx=(z1x+z2x)*0.5f, zy=(z1y+z2y)*0.5f;
    float o0=bsh[lane], o1=bsh[lane+32];
    #pragma unroll
    for (int kk=0;kk<32;kk++){
      float b0=__shfl_sync(FULL,zx,kk);
      float b1=__shfl_sync(FULL,zy,kk);
      float4 w = Wq[kk*32+lane];
      o0 += b0*w.x + b1*w.z;
      o1 += b0*w.y + b1*w.w;
    }
    g_y[row*64+lane]=o0; g_y[row*64+lane+32]=o1;
    ls0+=o0; lq0+=o0*o0; ls1+=o1; lq1+=o1*o1;
  }
  atomicAdd(&sy[lane],ls0);    atomicAdd(&sy[lane+32],ls1);
  atomicAdd(&sq[lane],lq0);    atomicAdd(&sq[lane+32],lq1);
  __syncthreads();
  if (tid<64){ atomicAdd(&g_stats[256+tid],sy[tid]); atomicAdd(&g_stats[320+tid],sq[tid]); }
}

// final: BN(y) -> relu -> @Wm2 + bm2 ; tail re-zeroes g_deg for next replay.
__global__ void __launch_bounds__(256) k_final(
    const float* __restrict__ Wm2, const float* __restrict__ bm2,
    const float* __restrict__ gamma, const float* __restrict__ beta,
    float* __restrict__ outp){
  __shared__ float4 Wq[1024];
  __shared__ float sc[64], shf[64];
  __shared__ float bsh[64];
  int tid=threadIdx.x;
  for (int idx=tid; idx<1024; idx+=256){
    int kk=idx>>5, j=idx&31;
    float wx = Wm2[(2*kk)*40+j];
    float wy = (j<8)? Wm2[(2*kk)*40+j+32]   : 0.f;
    float wz = Wm2[(2*kk+1)*40+j];
    float ww = (j<8)? Wm2[(2*kk+1)*40+j+32] : 0.f;
    Wq[idx]=make_float4(wx,wy,wz,ww);
  }
  if (tid<64){
    double s=(double)g_stats[256+tid], q=(double)g_stats[320+tid];
    double mu=s/(double)Nn;
    double var=q/(double)Nn - mu*mu;
    float inv=(float)(1.0/sqrt(var+1e-5));
    float scl=gamma[tid]*inv;
    sc[tid]=scl;
    shf[tid]=beta[tid]-(float)mu*scl;
    bsh[tid]=(tid<40)? bm2[tid] : 0.f;
  }
  __syncthreads();
  int lane=tid&31;
  int warp=(blockIdx.x*blockDim.x+tid)>>5;
  int nw  =(gridDim.x*blockDim.x)>>5;
  const float2* yv = (const float2*)g_y;
  float scx=sc[2*lane], scy=sc[2*lane+1], shx=shf[2*lane], shy=shf[2*lane+1];
  for (int row=warp; row<Nn; row+=nw){
    float2 y = yv[row*32+lane];
    float yb0=fmaxf(y.x*scx+shx, 0.f);
    float yb1=fmaxf(y.y*scy+shy, 0.f);
    float p0=bsh[lane];
    float p1=bsh[32+lane];
    #pragma unroll
    for (int kk=0;kk<32;kk++){
      float b0=__shfl_sync(FULL,yb0,kk);
      float b1=__shfl_sync(FULL,yb1,kk);
      float4 w = Wq[kk*32+lane];
      p0 += b0*w.x + b1*w.z;
      p1 += b0*w.y + b1*w.w;
    }
    outp[row*40+lane]=p0;
    if (lane<8) outp[row*40+32+lane]=p1;
  }
  // re-zero degree counters for the next graph replay
  int gt = blockIdx.x*blockDim.x + tid;
  for (int j=gt; j<4*Nn; j+=gridDim.x*blockDim.x) g_deg[j]=0;
}

// ---------------- launch ----------------
extern "C" void kernel_launch(void* const* d_in, const int* in_sizes, int n_in,
                              void* d_out, int out_size){
  const float* feat1=(const float*)d_in[0];
  const int*   src1 =(const int*)  d_in[1];
  const int*   dst1 =(const int*)  d_in[2];
  const float* feat2=(const float*)d_in[3];
  const int*   src2 =(const int*)  d_in[4];
  const int*   dst2 =(const int*)  d_in[5];
  const float* W1a=(const float*)d_in[6];  const float* b1a=(const float*)d_in[7];
  const float* W1b=(const float*)d_in[8];  const float* b1b=(const float*)d_in[9];
  const float* W2a=(const float*)d_in[10]; const float* b2a=(const float*)d_in[11];
  const float* W2b=(const float*)d_in[12]; const float* b2b=(const float*)d_in[13];
  const float* Wm1=(const float*)d_in[14]; const float* bm1=(const float*)d_in[15];
  const float* gamma=(const float*)d_in[16]; const float* beta=(const float*)d_in[17];
  const float* Wm2=(const float*)d_in[18]; const float* bm2=(const float*)d_in[19];
  float* out=(float*)d_out;

  k_degrank<<<(Ee/4+255)/256,256>>>((const int4*)src1,(const int4*)dst1,
                                    (const int4*)src2,(const int4*)dst2);
  k_scan1<<<2*NBLK,1024>>>();
  k_fillpre<<<(2*Ee + 2*Nn*16 + 2*(Nn+1) + 255)/256,256>>>(
      src1,dst1,src2,dst2,(const float4*)feat1,(const float4*)feat2);
  k_convA<<<2*KB,256>>>(W1a,b1a,W2a,b2a);
  k_convB<<<2*KB,256>>>(W1b,b1b,W2b,b2b);
  k_zy<<<GB,256>>>(Wm1,bm1,out);
  k_final<<<GB,256>>>(Wm2,bm2,gamma,beta,out + 2u*Nn*64);
}

// round 15
// speedup vs baseline: 1.0794x; 1.0794x over previous
#include <cuda_runtime.h>
#include <cuda_fp16.h>
#include <cstdint>

#define Nn 100000
#define Ee 1600000
#define NBLK 98            // ceil(Nn/1024)
#define FULL 0xffffffffu
#define PB 592             // persistent conv blocks (4 per SM * 148)
#define NT 6250            // 16-row tiles per graph
#define NW (PB*8)          // persistent warps
#define GB 1184

// ---------------- scratch (static __device__, zero-initialized) ----------------
__device__ int    g_deg[4*Nn];         // out1, in1, out2, in2 (re-zeroed by k_final tail)
__device__ float  g_norm[4*Nn];        // ns1, nd1, ns2, nd2
__device__ int    g_rp[2*(Nn+1)];      // partial CSR row ptrs (scan1 block-local)
__device__ int    g_rpf[2*(Nn+1)];     // final CSR row ptrs
__device__ int    g_col[2*Ee];         // (src*32) per dst-sorted edge
__device__ int    g_rank[2*Ee];        // per-edge rank within dst bucket
__device__ int    g_bsum[2*NBLK];      // scan block sums
__device__ __half g_sxA[2*Nn*64];
__device__ __half g_sxB[2*Nn*64];
__device__ float  g_h[2*Nn*64];
__device__ float  g_y[Nn*64];
__device__ float  g_stats[384];

// degree count + in-bucket rank recording (4 edges/thread, int4)
__global__ void k_degrank(const int4* __restrict__ s1, const int4* __restrict__ d1,
                          const int4* __restrict__ s2, const int4* __restrict__ d2){
  int t = blockIdx.x*blockDim.x + threadIdx.x;
  if (t >= Ee/4) return;
  int4 a=s1[t], b=d1[t], c=s2[t], d=d2[t];
  atomicAdd(&g_deg[a.x],1); atomicAdd(&g_deg[a.y],1);
  atomicAdd(&g_deg[a.z],1); atomicAdd(&g_deg[a.w],1);
  int4 r1;
  r1.x=atomicAdd(&g_deg[Nn+b.x],1); r1.y=atomicAdd(&g_deg[Nn+b.y],1);
  r1.z=atomicAdd(&g_deg[Nn+b.z],1); r1.w=atomicAdd(&g_deg[Nn+b.w],1);
  ((int4*)g_rank)[t]=r1;
  atomicAdd(&g_deg[2*Nn+c.x],1); atomicAdd(&g_deg[2*Nn+c.y],1);
  atomicAdd(&g_deg[2*Nn+c.z],1); atomicAdd(&g_deg[2*Nn+c.w],1);
  int4 r2;
  r2.x=atomicAdd(&g_deg[3*Nn+d.x],1); r2.y=atomicAdd(&g_deg[3*Nn+d.y],1);
  r2.z=atomicAdd(&g_deg[3*Nn+d.z],1); r2.w=atomicAdd(&g_deg[3*Nn+d.w],1);
  ((int4*)(g_rank+Ee))[t]=r2;
}

// block-local inclusive scan of in-degree + norms
__global__ void k_scan1(){
  __shared__ int sh[1024];
  int g = blockIdx.x / NBLK;
  int b = blockIdx.x - g*NBLK;
  const int* degin  = g_deg + 2*Nn*g + Nn;
  const int* degout = g_deg + 2*Nn*g;
  int* rp = g_rp + g*(Nn+1);
  int t = threadIdx.x;
  int i = b*1024 + t;
  int v = (i<Nn)? degin[i] : 0;
  if (i<Nn){
    int dou = degout[i]; if (dou<1) dou=1;
    int din = v;         if (din<1) din=1;
    g_norm[2*Nn*g + i]      = rsqrtf((float)dou);   // ns
    g_norm[2*Nn*g + Nn + i] = rsqrtf((float)din);   // nd
  }
  sh[t]=v; __syncthreads();
  #pragma unroll
  for (int off=1; off<1024; off<<=1){
    int x = (t>=off)? sh[t-off] : 0;
    __syncthreads();
    sh[t]+=x;
    __syncthreads();
  }
  if (i<Nn) rp[i] = sh[t]-v;                  // block-local exclusive
  if (t==1023) g_bsum[g*NBLK + b] = sh[t];
}

// fused: per-block redundant bsum scan + CSR fill (atomic-free) + final rp + prescale + stats zero
__global__ void __launch_bounds__(256) k_fillpre(
    const int* __restrict__ s1, const int* __restrict__ d1,
    const int* __restrict__ s2, const int* __restrict__ d2,
    const float4* __restrict__ x1, const float4* __restrict__ x2){
  __shared__ int sh[256];
  __shared__ int pref[256];    // pref[g*128 + blk] = exclusive prefix of bsum
  int tid = threadIdx.x;
  int h = tid>>7, li = tid&127;
  int v = (li<NBLK)? g_bsum[h*NBLK+li] : 0;
  sh[tid]=v; __syncthreads();
  #pragma unroll
  for (int off=1; off<128; off<<=1){
    int x = (li>=off)? sh[tid-off] : 0;
    __syncthreads();
    sh[tid]+=x;
    __syncthreads();
  }
  pref[tid] = sh[tid]-v;
  __syncthreads();
  int t = blockIdx.x*256 + tid;
  if (t < 384) g_stats[t]=0.f;
  if (t < 2*Ee){
    int g = t >= Ee;
    int e = t - g*Ee;
    int d = g ? d2[e] : d1[e];
    int s = g ? s2[e] : s1[e];
    int pos = g_rp[g*(Nn+1)+d] + pref[g*128 + (d>>10)] + g_rank[g*Ee+e];
    g_col[g*Ee+pos] = s*32;
  } else if (t < 2*Ee + 2*Nn*16){
    int i = t - 2*Ee;
    int g = i >= Nn*16;
    int local = i - g*Nn*16;
    float s = g_norm[2*Nn*g + (local>>4)];
    float4 vv = g ? x2[local] : x1[local];
    __half2 h0 = __floats2half2_rn(vv.x*s, vv.y*s);
    __half2 h1 = __floats2half2_rn(vv.z*s, vv.w*s);
    union { __half2 hh[2]; uint2 u; } pk;
    pk.hh[0]=h0; pk.hh[1]=h1;
    ((uint2*)g_sxA)[i] = pk.u;
  } else {
    int i2 = t - (2*Ee + 2*Nn*16);
    if (i2 < 2*(Nn+1)){
      int g = i2 >= (Nn+1);
      int i = i2 - g*(Nn+1);
      g_rpf[g*(Nn+1)+i] = (i==Nn)? Ee : (g_rp[g*(Nn+1)+i] + pref[g*128 + (i>>10)]);
    }
  }
}

// gather: 16-deep unroll (direct col loads, MLP=16), then 4, then 1. col pre-scaled (*32).
#define GATHER16(sx, rp, col, row, ax, ay)                              \
  { int e0=rp[row], e1=rp[row+1]; int e=e0;                             \
    for (; e+16<=e1; e+=16){                                            \
      int cc[16]; __half2 pp[16];                                       \
      _Pragma("unroll")                                                 \
      for (int q=0;q<16;q++) cc[q]=col[e+q];                            \
      _Pragma("unroll")                                                 \
      for (int q=0;q<16;q++) pp[q]=sx[cc[q]+lane];                      \
      float sx0=0.f, sy0=0.f;                                           \
      _Pragma("unroll")                                                 \
      for (int q=0;q<16;q++){                                           \
        float2 v=__half22float2(pp[q]); sx0+=v.x; sy0+=v.y;             \
      }                                                                 \
      ax+=sx0; ay+=sy0;                                                 \
    }                                                                   \
    for (; e+4<=e1; e+=4){                                              \
      int c0=col[e],c1=col[e+1],c2=col[e+2],c3=col[e+3];                \
      __half2 p0=sx[c0+lane], p1=sx[c1+lane];                           \
      __half2 p2=sx[c2+lane], p3=sx[c3+lane];                           \
      float2 v0=__half22float2(p0), v1=__half22float2(p1);              \
      float2 v2=__half22float2(p2), v3=__half22float2(p3);              \
      ax += (v0.x+v1.x)+(v2.x+v3.x);                                    \
      ay += (v0.y+v1.y)+(v2.y+v3.y);                                    \
    }                                                                   \
    for (; e<e1; e++){                                                  \
      int c=col[e]; float2 v=__half22float2(sx[c+lane]);                \
      ax+=v.x; ay+=v.y;                                                 \
    } }

#define LDMX4(a0,a1,a2,a3,addr)                                         \
  asm volatile("ldmatrix.sync.aligned.m8n8.x4.shared.b16 {%0,%1,%2,%3}, [%4];" \
    : "=r"(a0),"=r"(a1),"=r"(a2),"=r"(a3) : "r"(addr))

#define LDMX4T(b0,b1,b2,b3,addr)                                        \
  asm volatile("ldmatrix.sync.aligned.m8n8.x4.trans.shared.b16 {%0,%1,%2,%3}, [%4];" \
    : "=r"(b0),"=r"(b1),"=r"(b2),"=r"(b3) : "r"(addr))

#define MMA16816(d, a0,a1,a2,a3, b0,b1)                                 \
  asm volatile("mma.sync.aligned.m16n8k16.row.col.f32.f16.f16.f32 "     \
    "{%0,%1,%2,%3}, {%4,%5,%6,%7}, {%8,%9}, {%0,%1,%2,%3};"             \
    : "+f"(d[0]),"+f"(d[1]),"+f"(d[2]),"+f"(d[3])                       \
    : "r"(a0),"r"(a1),"r"(a2),"r"(a3), "r"(b0),"r"(b1))

// W-split df16 GEMM core: acc = A*Wh + A*Wl
#define MMA_TILE_WSPLIT(acc, aAddr, wH, wL)                             \
  { _Pragma("unroll")                                                   \
    for (int s=0;s<4;s++){                                              \
      unsigned int a0,a1,a2,a3;                                         \
      LDMX4(a0,a1,a2,a3, (aAddr) + s*32);                               \
      _Pragma("unroll")                                                 \
      for (int jj=0;jj<4;jj++){                                         \
        unsigned int bh0,bh1,bh2,bh3, bl0,bl1,bl2,bl3;                  \
        LDMX4T(bh0,bh1,bh2,bh3, (wH) + s*2048 + jj*32);                 \
        LDMX4T(bl0,bl1,bl2,bl3, (wL) + s*2048 + jj*32);                 \
        MMA16816(acc[2*jj],   a0,a1,a2,a3, bh0,bh1);                    \
        MMA16816(acc[2*jj],   a0,a1,a2,a3, bl0,bl1);                    \
        MMA16816(acc[2*jj+1], a0,a1,a2,a3, bh2,bh3);                    \
        MMA16816(acc[2*jj+1], a0,a1,a2,a3, bl2,bl3);                    \
      }                                                                 \
    } }

// persistent fused conv layer 1 (HMMA, W-split), both graphs in one launch
__global__ void __launch_bounds__(256,4) k_convA(
    const float* __restrict__ W1,const float* __restrict__ B1,
    const float* __restrict__ W2,const float* __restrict__ B2){
  __shared__ __half  WshH[2][4096], WshL[2][4096];   // per-graph W hi/lo
  __shared__ float   bsh[128];
  __shared__ __half2 As[8*512];
  int tid=threadIdx.x;
  for (int j=tid;j<4096;j+=256){
    float wa=W1[j], wb=W2[j];
    __half ha=__float2half_rn(wa), hb=__float2half_rn(wb);
    WshH[0][j]=ha; WshL[0][j]=__float2half_rn(wa-__half2float(ha));
    WshH[1][j]=hb; WshL[1][j]=__float2half_rn(wb-__half2float(hb));
  }
  if (tid<64) bsh[tid]=B1[tid];
  else if (tid<128) bsh[tid]=B2[tid-64];
  __syncthreads();
  int lane=tid&31, wid=tid>>5;
  __half2* myA = As + wid*512;
  unsigned int aBase = (unsigned int)__cvta_generic_to_shared(myA);
  unsigned int wBase0H = (unsigned int)__cvta_generic_to_shared(WshH[0]);
  unsigned int wBase0L = (unsigned int)__cvta_generic_to_shared(WshL[0]);
  int gwarp = blockIdx.x*8 + wid;
  for (int t=gwarp; t<2*NT; t+=NW){
    int g = t >= NT;
    int lt = t - g*NT;
    int R0 = lt*16;
    const int* rp  = g_rpf + g*(Nn+1);
    const int* col = g_col + g*Ee;
    const __half2* sx = (const __half2*)g_sxA + g*Nn*32;
    __half2* outp = (__half2*)g_sxB + g*Nn*32;
    const float* nd = g_norm + Nn + 2*Nn*g;
    const float* ns = g_norm + 2*Nn*g;
    __syncwarp();
    for (int r=0;r<16;r++){
      int row=R0+r;
      float ax=0.f, ay=0.f;
      GATHER16(sx, rp, col, row, ax, ay);
      myA[r*32+lane]=__floats2half2_rn(ax,ay);
    }
    __syncwarp();
    float acc[8][4];
    #pragma unroll
    for (int j=0;j<8;j++){ acc[j][0]=0.f;acc[j][1]=0.f;acc[j][2]=0.f;acc[j][3]=0.f; }
    unsigned int aA = aBase + (lane&15)*128 + (lane>>4)*16;
    unsigned int wH = wBase0H + g*8192u + (lane&15)*128 + (lane>>4)*16;
    unsigned int wL = wBase0L + g*8192u + (lane&15)*128 + (lane>>4)*16;
    MMA_TILE_WSPLIT(acc, aA, wH, wL);
    int r0 = lane>>2;
    int row0 = R0 + r0, row1 = row0 + 8;
    float nd0=nd[row0], nd1=nd[row1], ns0=ns[row0], ns1=ns[row1];
    const float* bs = bsh + g*64;
    #pragma unroll
    for (int j=0;j<8;j++){
      int c0 = j*8 + (lane&3)*2;
      float bb0=bs[c0], bb1=bs[c0+1];
      float o00=fmaxf(acc[j][0]*nd0+bb0,0.f)*ns0;
      float o01=fmaxf(acc[j][1]*nd0+bb1,0.f)*ns0;
      float o10=fmaxf(acc[j][2]*nd1+bb0,0.f)*ns1;
      float o11=fmaxf(acc[j][3]*nd1+bb1,0.f)*ns1;
      outp[row0*32 + (c0>>1)] = __floats2half2_rn(o00,o01);
      outp[row1*32 + (c0>>1)] = __floats2half2_rn(o10,o11);
    }
  }
}

// persistent fused conv layer 2 (HMMA, W-split) + per-graph stats
__global__ void __launch_bounds__(256,4) k_convB(
    const float* __restrict__ W1,const float* __restrict__ B1,
    const float* __restrict__ W2,const float* __restrict__ B2){
  __shared__ __half  WshH[2][4096], WshL[2][4096];
  __shared__ float   bsh[128];
  __shared__ __half2 As[8*512];
  __shared__ float   shs[128], shq[128];   // per-graph column stats
  int tid=threadIdx.x;
  for (int j=tid;j<4096;j+=256){
    float wa=W1[j], wb=W2[j];
    __half ha=__float2half_rn(wa), hb=__float2half_rn(wb);
    WshH[0][j]=ha; WshL[0][j]=__float2half_rn(wa-__half2float(ha));
    WshH[1][j]=hb; WshL[1][j]=__float2half_rn(wb-__half2float(hb));
  }
  if (tid<64) bsh[tid]=B1[tid];
  else if (tid<128) bsh[tid]=B2[tid-64];
  if (tid<128){ shs[tid]=0.f; shq[tid]=0.f; }
  __syncthreads();
  int lane=tid&31, wid=tid>>5;
  __half2* myA = As + wid*512;
  unsigned int aBase = (unsigned int)__cvta_generic_to_shared(myA);
  unsigned int wBase0H = (unsigned int)__cvta_generic_to_shared(WshH[0]);
  unsigned int wBase0L = (unsigned int)__cvta_generic_to_shared(WshL[0]);
  int gwarp = blockIdx.x*8 + wid;
  for (int t=gwarp; t<2*NT; t+=NW){
    int g = t >= NT;
    int lt = t - g*NT;
    int R0 = lt*16;
    const int* rp  = g_rpf + g*(Nn+1);
    const int* col = g_col + g*Ee;
    const __half2* sx = (const __half2*)g_sxB + g*Nn*32;
    float2* outp = (float2*)(g_h + g*Nn*64);
    const float* nd = g_norm + Nn + 2*Nn*g;
    __syncwarp();
    for (int r=0;r<16;r++){
      int row=R0+r;
      float ax=0.f, ay=0.f;
      GATHER16(sx, rp, col, row, ax, ay);
      myA[r*32+lane]=__floats2half2_rn(ax,ay);
    }
    __syncwarp();
    float acc[8][4];
    #pragma unroll
    for (int j=0;j<8;j++){ acc[j][0]=0.f;acc[j][1]=0.f;acc[j][2]=0.f;acc[j][3]=0.f; }
    unsigned int aA = aBase + (lane&15)*128 + (lane>>4)*16;
    unsigned int wH = wBase0H + g*8192u + (lane&15)*128 + (lane>>4)*16;
    unsigned int wL = wBase0L + g*8192u + (lane&15)*128 + (lane>>4)*16;
    MMA_TILE_WSPLIT(acc, aA, wH, wL);
    int r0 = lane>>2;
    int row0 = R0 + r0, row1 = row0 + 8;
    float nd0=nd[row0], nd1=nd[row1];
    const float* bs = bsh + g*64;
    #pragma unroll
    for (int j=0;j<8;j++){
      int c0 = j*8 + (lane&3)*2;
      float bb0=bs[c0], bb1=bs[c0+1];
      float o00=acc[j][0]*nd0+bb0;
      float o01=acc[j][1]*nd0+bb1;
      float o10=acc[j][2]*nd1+bb0;
      float o11=acc[j][3]*nd1+bb1;
      outp[row0*32 + (c0>>1)] = make_float2(o00,o01);
      outp[row1*32 + (c0>>1)] = make_float2(o10,o11);
      // per-tile stats reduce (lanes sharing a column differ in bits 2..4)
      float s0=o00+o10, s1=o01+o11, q0=o00*o00+o10*o10, q1=o01*o01+o11*o11;
      #pragma unroll
      for (int m=4;m<32;m<<=1){
        s0 += __shfl_xor_sync(FULL, s0, m);
        s1 += __shfl_xor_sync(FULL, s1, m);
        q0 += __shfl_xor_sync(FULL, q0, m);
        q1 += __shfl_xor_sync(FULL, q1, m);
      }
      if (lane<4){
        int c = g*64 + j*8 + lane*2;
        atomicAdd(&shs[c],   s0);
        atomicAdd(&shs[c+1], s1);
        atomicAdd(&shq[c],   q0);
        atomicAdd(&shq[c+1], q1);
      }
    }
  }
  __syncthreads();
  if (tid<128){
    int g = tid>>6, c = tid&63;
    atomicAdd(&g_stats[g*128+c],    shs[tid]);
    atomicAdd(&g_stats[g*128+64+c], shq[tid]);
  }
}

// z1,z2 out; z=(z1+z2)/2; y=z@Wm1+bm1; BN stats of y.
__global__ void __launch_bounds__(256) k_zy(
    const float* __restrict__ Wm1, const float* __restrict__ bm1,
    float* __restrict__ out){
  __shared__ float4 Wq[1024];
  __shared__ float cf[256];
  __shared__ float bsh[64];
  __shared__ float sy[64], sq[64];
  int tid=threadIdx.x;
  for (int idx=tid; idx<1024; idx+=256){
    int kk=idx>>5, j=idx&31;
    Wq[idx]=make_float4(Wm1[(2*kk)*64+j],   Wm1[(2*kk)*64+j+32],
                        Wm1[(2*kk+1)*64+j], Wm1[(2*kk+1)*64+j+32]);
  }
  if (tid<64){
    bsh[tid]=bm1[tid]; sy[tid]=0.f; sq[tid]=0.f;
    #pragma unroll
    for (int gg=0; gg<2; gg++){
      double s = (double)g_stats[gg*128+tid];
      double q = (double)g_stats[gg*128+64+tid];
      double mean = s/(double)Nn;
      double var  = (q - s*s/(double)Nn)/(double)(Nn-1);   // ddof=1
      float is = (float)(1.0/sqrt(var));
      cf[gg*128+tid]    = is;
      cf[gg*128+64+tid] = (float)(-mean)*is;
    }
  }
  __syncthreads();
  int lane=tid&31;
  int warp=(blockIdx.x*blockDim.x+tid)>>5;
  int nw  =(gridDim.x*blockDim.x)>>5;
  const float2* h1 = (const float2*)g_h;
  const float2* h2 = (const float2*)(g_h + Nn*64);
  float2* oz1 = (float2*)out;
  float2* oz2 = (float2*)(out + Nn*64);
  float ls0=0.f,lq0=0.f,ls1=0.f,lq1=0.f;
  int k0=2*lane, k1=2*lane+1;
  float a1x=cf[k0],     a1y=cf[k1],     b1x=cf[64+k0],  b1y=cf[64+k1];
  float a2x=cf[128+k0], a2y=cf[128+k1], b2x=cf[192+k0], b2y=cf[192+k1];
  for (int row=warp; row<Nn; row+=nw){
    float2 v1=h1[row*32+lane], v2=h2[row*32+lane];
    float z1x=v1.x*a1x+b1x, z1y=v1.y*a1y+b1y;
    float z2x=v2.x*a2x+b2x, z2y=v2.y*a2y+b2y;
    oz1[row*32+lane]=make_float2(z1x,z1y);
    oz2[row*32+lane]=make_float2(z2x,z2y);
    float zx=(z1x+z2x)*0.5f, zy=(z1y+z2y)*0.5f;
    float o0=bsh[lane], o1=bsh[lane+32];
    #pragma unroll
    for (int kk=0;kk<32;kk++){
      float b0=__shfl_sync(FULL,zx,kk);
      float b1=__shfl_sync(FULL,zy,kk);
      float4 w = Wq[kk*32+lane];
      o0 += b0*w.x + b1*w.z;
      o1 += b0*w.y + b1*w.w;
    }
    g_y[row*64+lane]=o0; g_y[row*64+lane+32]=o1;
    ls0+=o0; lq0+=o0*o0; ls1+=o1; lq1+=o1*o1;
  }
  atomicAdd(&sy[lane],ls0);    atomicAdd(&sy[lane+32],ls1);
  atomicAdd(&sq[lane],lq0);    atomicAdd(&sq[lane+32],lq1);
  __syncthreads();
  if (tid<64){ atomicAdd(&g_stats[256+tid],sy[tid]); atomicAdd(&g_stats[320+tid],sq[tid]); }
}

// final: BN(y) -> relu -> @Wm2 + bm2 ; tail re-zeroes g_deg for next replay.
__global__ void __launch_bounds__(256) k_final(
    const float* __restrict__ Wm2, const float* __restrict__ bm2,
    const float* __restrict__ gamma, const float* __restrict__ beta,
    float* __restrict__ outp){
  __shared__ float4 Wq[1024];
  __shared__ float sc[64], shf[64];
  __shared__ float bsh[64];
  int tid=threadIdx.x;
  for (int idx=tid; idx<1024; idx+=256){
    int kk=idx>>5, j=idx&31;
    float wx = Wm2[(2*kk)*40+j];
    float wy = (j<8)? Wm2[(2*kk)*40+j+32]   : 0.f;
    float wz = Wm2[(2*kk+1)*40+j];
    float ww = (j<8)? Wm2[(2*kk+1)*40+j+32] : 0.f;
    Wq[idx]=make_float4(wx,wy,wz,ww);
  }
  if (tid<64){
    double s=(double)g_stats[256+tid], q=(double)g_stats[320+tid];
    double mu=s/(double)Nn;
    double var=q/(double)Nn - mu*mu;
    float inv=(float)(1.0/sqrt(var+1e-5));
    float scl=gamma[tid]*inv;
    sc[tid]=scl;
    shf[tid]=beta[tid]-(float)mu*scl;
    bsh[tid]=(tid<40)? bm2[tid] : 0.f;
  }
  __syncthreads();
  int lane=tid&31;
  int warp=(blockIdx.x*blockDim.x+tid)>>5;
  int nw  =(gridDim.x*blockDim.x)>>5;
  const float2* yv = (const float2*)g_y;
  float scx=sc[2*lane], scy=sc[2*lane+1], shx=shf[2*lane], shy=shf[2*lane+1];
  for (int row=warp; row<Nn; row+=nw){
    float2 y = yv[row*32+lane];
    float yb0=fmaxf(y.x*scx+shx, 0.f);
    float yb1=fmaxf(y.y*scy+shy, 0.f);
    float p0=bsh[lane];
    float p1=bsh[32+lane];
    #pragma unroll
    for (int kk=0;kk<32;kk++){
      float b0=__shfl_sync(FULL,yb0,kk);
      float b1=__shfl_sync(FULL,yb1,kk);
      float4 w = Wq[kk*32+lane];
      p0 += b0*w.x + b1*w.z;
      p1 += b0*w.y + b1*w.w;
    }
    outp[row*40+lane]=p0;
    if (lane<8) outp[row*40+32+lane]=p1;
  }
  // re-zero degree counters for the next graph replay
  int gt = blockIdx.x*blockDim.x + tid;
  for (int j=gt; j<4*Nn; j+=gridDim.x*blockDim.x) g_deg[j]=0;
}

// ---------------- launch ----------------
extern "C" void kernel_launch(void* const* d_in, const int* in_sizes, int n_in,
                              void* d_out, int out_size){
  const float* feat1=(const float*)d_in[0];
  const int*   src1 =(const int*)  d_in[1];
  const int*   dst1 =(const int*)  d_in[2];
  const float* feat2=(const float*)d_in[3];
  const int*   src2 =(const int*)  d_in[4];
  const int*   dst2 =(const int*)  d_in[5];
  const float* W1a=(const float*)d_in[6];  const float* b1a=(const float*)d_in[7];
  const float* W1b=(const float*)d_in[8];  const float* b1b=(const float*)d_in[9];
  const float* W2a=(const float*)d_in[10]; const float* b2a=(const float*)d_in[11];
  const float* W2b=(const float*)d_in[12]; const float* b2b=(const float*)d_in[13];
  const float* Wm1=(const float*)d_in[14]; const float* bm1=(const float*)d_in[15];
  const float* gamma=(const float*)d_in[16]; const float* beta=(const float*)d_in[17];
  const float* Wm2=(const float*)d_in[18]; const float* bm2=(const float*)d_in[19];
  float* out=(float*)d_out;

  k_degrank<<<(Ee/4+255)/256,256>>>((const int4*)src1,(const int4*)dst1,
                                    (const int4*)src2,(const int4*)dst2);
  k_scan1<<<2*NBLK,1024>>>();
  k_fillpre<<<(2*Ee + 2*Nn*16 + 2*(Nn+1) + 255)/256,256>>>(
      src1,dst1,src2,dst2,(const float4*)feat1,(const float4*)feat2);
  k_convA<<<PB,256>>>(W1a,b1a,W2a,b2a);
  k_convB<<<PB,256>>>(W1b,b1b,W2b,b2b);
  k_zy<<<GB,256>>>(Wm1,bm1,out);
  k_final<<<GB,256>>>(Wm2,bm2,gamma,beta,out + 2u*Nn*64);
}